// round 6
// baseline (speedup 1.0000x reference)
#include <cuda_runtime.h>
#include <cuda_bf16.h>

// Problem constants
#define BATCH 128
#define BINS 128
#define HW 262144               // 512*512 elements per batch (C=1)
#define TOTAL (BATCH * HW)      // 33554432
#define HIST_BPB 16             // histogram blocks per batch
#define HIST_THREADS 128
#define CHUNK (HW / HIST_BPB)   // 16384 elements per hist block

// Scratch (device globals: no allocations allowed)
// TRANSPOSED layout: g_part[part][bin][batch] so the MLP reads are coalesced
// across threads (thread = batch).
__device__ float g_part[HIST_BPB * BINS * BATCH];
__device__ float g_w[BATCH];

// ---------------------------------------------------------------------------
// Kernel 1: per-batch histogram.
// Per-thread private UINT8 counters in shared memory (16 KB/block -> ~13
// blocks/SM, vs 32 KB/6 blocks in R5: occupancy was the binder, the kernel is
// chain-latency bound, nothing saturated).
//   counter(bin, t) at byte index  bin*128 + (t&31)*4 + (t>>5)
// -> within a warp: word index = bin*32 + (t&31): distinct word AND distinct
//    bank per lane (bank = t&31, independent of bin). Warps 0..3 share words
//    but write different bytes (separate instructions). Zero conflicts.
// Each thread handles CHUNK/128 = 128 elements -> uint8 max count 128 < 255.
// ---------------------------------------------------------------------------
__global__ void __launch_bounds__(HIST_THREADS) hist_kernel(const float* __restrict__ x) {
    __shared__ unsigned char sh[BINS * HIST_THREADS];    // 16 KB
    unsigned int* sh32 = reinterpret_cast<unsigned int*>(sh);

    const int t = threadIdx.x;

    // zero: 4096 words / 128 threads = 32 each, bank = t&31: conflict-free
    #pragma unroll
    for (int i = 0; i < 32; i++)
        sh32[i * HIST_THREADS + t] = 0u;
    __syncthreads();

    const int batch = blockIdx.x >> 4;              // / HIST_BPB
    const int part  = blockIdx.x & (HIST_BPB - 1);
    const int lane_off = (t & 31) * 4 + (t >> 5);   // byte offset within a bin row

    const float4* xp = reinterpret_cast<const float4*>(x)
                     + (size_t)batch * (HW / 4) + (size_t)part * (CHUNK / 4);

    // CHUNK/4 = 4096 float4 per block, 128 threads -> 32 iterations
    #pragma unroll 8
    for (int i = t; i < CHUNK / 4; i += HIST_THREADS) {
        float4 v = xp[i];
        {
            float g = v.x * 128.0f;                  // exact (x * 2^7)
            int bin = min(__float2int_rd(g), BINS - 1);
            if (g >= 0.0f && g <= 128.0f) sh[bin * HIST_THREADS + lane_off]++;
        }
        {
            float g = v.y * 128.0f;
            int bin = min(__float2int_rd(g), BINS - 1);
            if (g >= 0.0f && g <= 128.0f) sh[bin * HIST_THREADS + lane_off]++;
        }
        {
            float g = v.z * 128.0f;
            int bin = min(__float2int_rd(g), BINS - 1);
            if (g >= 0.0f && g <= 128.0f) sh[bin * HIST_THREADS + lane_off]++;
        }
        {
            float g = v.w * 128.0f;
            int bin = min(__float2int_rd(g), BINS - 1);
            if (g >= 0.0f && g <= 128.0f) sh[bin * HIST_THREADS + lane_off]++;
        }
    }
    __syncthreads();

    // Reduce: thread t sums bin t's 128 counters = 32 words x 4 bytes each.
    // dp4a(word, 0x01010101) sums the 4 unsigned bytes in one instruction.
    // Rotated read j=(t+i)&31 -> bank j: distinct per lane, conflict-free.
    unsigned int s = 0;
    #pragma unroll
    for (int i = 0; i < 32; i++) {
        int j = (t + i) & 31;
        s = __dp4a(sh32[t * 32 + j], 0x01010101u, s);
    }
    // transposed store: [part][bin=t][batch]
    g_part[(part * BINS + t) * BATCH + batch] = (float)s;
}

// ---------------------------------------------------------------------------
// Kernel 2: tiny MLP. One block, 128 threads; thread b handles batch b.
//   hist[b][k] = sum_p g_part[p][k][b]   <- COALESCED (b is the lane index)
//   h = relu(hist[b] @ W1 + b1)   (128x16)
//   w = h @ W2 + b2               (16x1)
// ---------------------------------------------------------------------------
__global__ void __launch_bounds__(BATCH) mlp_kernel(const float* __restrict__ W1,
                                                    const float* __restrict__ b1,
                                                    const float* __restrict__ W2,
                                                    const float* __restrict__ b2) {
    const int b = threadIdx.x;
    float h[16];
    #pragma unroll
    for (int j = 0; j < 16; j++) h[j] = b1[j];

    #pragma unroll 4
    for (int k = 0; k < BINS; k++) {
        float c = 0.0f;
        #pragma unroll
        for (int p = 0; p < HIST_BPB; p++)
            c += g_part[(p * BINS + k) * BATCH + b];
        #pragma unroll
        for (int j = 0; j < 16; j++)
            h[j] = fmaf(c, W1[k * 16 + j], h[j]);
    }

    float w = b2[0];
    #pragma unroll
    for (int j = 0; j < 16; j++)
        w = fmaf(fmaxf(h[j], 0.0f), W2[j], w);

    g_w[b] = w;
}

// ---------------------------------------------------------------------------
// Kernel 3: out = x * w[batch]. float4 vectorized; 65536 float4 per batch so
// batch = vec_idx >> 16 (warp-uniform).
// ---------------------------------------------------------------------------
__global__ void __launch_bounds__(256) scale_kernel(const float* __restrict__ x,
                                                    float* __restrict__ out) {
    size_t vi = (size_t)blockIdx.x * blockDim.x + threadIdx.x;
    float w = g_w[vi >> 16];
    float4 v = reinterpret_cast<const float4*>(x)[vi];
    v.x *= w; v.y *= w; v.z *= w; v.w *= w;
    reinterpret_cast<float4*>(out)[vi] = v;
}

// ---------------------------------------------------------------------------
// Launch
// ---------------------------------------------------------------------------
extern "C" void kernel_launch(void* const* d_in, const int* in_sizes, int n_in,
                              void* d_out, int out_size) {
    const float* x  = (const float*)d_in[0];
    const float* W1 = (const float*)d_in[1];
    const float* b1 = (const float*)d_in[2];
    const float* W2 = (const float*)d_in[3];
    const float* b2 = (const float*)d_in[4];
    float* out = (float*)d_out;

    hist_kernel<<<BATCH * HIST_BPB, HIST_THREADS>>>(x);
    mlp_kernel<<<1, BATCH>>>(W1, b1, W2, b2);
    scale_kernel<<<(TOTAL / 4) / 256, 256>>>(x, out);
}

// round 7
// speedup vs baseline: 3.4157x; 3.4157x over previous
#include <cuda_runtime.h>
#include <cuda_bf16.h>

// Problem constants
#define BATCH 128
#define BINS 128
#define HW 262144               // 512*512 elements per batch (C=1)
#define TOTAL (BATCH * HW)      // 33554432
#define HIST_BPB 16             // histogram blocks per batch
#define HIST_THREADS 128
#define CHUNK (HW / HIST_BPB)   // 16384 elements per hist block

// Scratch (device globals: no allocations allowed)
// Layout: g_part[part][batch][bin] -> hist epilogue store coalesced over bin,
// MLP per-bin loads coalesced over bin (thread = bin).
__device__ float g_part[HIST_BPB * BATCH * BINS];
__device__ float g_w[BATCH];

// ---------------------------------------------------------------------------
// Kernel 1: per-batch histogram (unchanged from R6: 32.9us, occ 63%).
// Per-thread private UINT8 counters in shared memory, conflict-free:
//   counter(bin, t) at byte index  bin*128 + (t&31)*4 + (t>>5)
// 16 KB/block -> ~13 blocks/SM. 128 elements/thread -> uint8 safe.
// ---------------------------------------------------------------------------
__global__ void __launch_bounds__(HIST_THREADS) hist_kernel(const float* __restrict__ x) {
    __shared__ unsigned char sh[BINS * HIST_THREADS];    // 16 KB
    unsigned int* sh32 = reinterpret_cast<unsigned int*>(sh);

    const int t = threadIdx.x;

    // zero: 4096 words / 128 threads = 32 each, bank = t&31: conflict-free
    #pragma unroll
    for (int i = 0; i < 32; i++)
        sh32[i * HIST_THREADS + t] = 0u;
    __syncthreads();

    const int batch = blockIdx.x >> 4;              // / HIST_BPB
    const int part  = blockIdx.x & (HIST_BPB - 1);
    const int lane_off = (t & 31) * 4 + (t >> 5);   // byte offset within a bin row

    const float4* xp = reinterpret_cast<const float4*>(x)
                     + (size_t)batch * (HW / 4) + (size_t)part * (CHUNK / 4);

    // CHUNK/4 = 4096 float4 per block, 128 threads -> 32 iterations
    #pragma unroll 8
    for (int i = t; i < CHUNK / 4; i += HIST_THREADS) {
        float4 v = xp[i];
        {
            float g = v.x * 128.0f;                  // exact (x * 2^7)
            int bin = min(__float2int_rd(g), BINS - 1);
            if (g >= 0.0f && g <= 128.0f) sh[bin * HIST_THREADS + lane_off]++;
        }
        {
            float g = v.y * 128.0f;
            int bin = min(__float2int_rd(g), BINS - 1);
            if (g >= 0.0f && g <= 128.0f) sh[bin * HIST_THREADS + lane_off]++;
        }
        {
            float g = v.z * 128.0f;
            int bin = min(__float2int_rd(g), BINS - 1);
            if (g >= 0.0f && g <= 128.0f) sh[bin * HIST_THREADS + lane_off]++;
        }
        {
            float g = v.w * 128.0f;
            int bin = min(__float2int_rd(g), BINS - 1);
            if (g >= 0.0f && g <= 128.0f) sh[bin * HIST_THREADS + lane_off]++;
        }
    }
    __syncthreads();

    // Reduce: thread t sums bin t's 128 counters = 32 words x 4 bytes (dp4a).
    // Rotated read j=(t+i)&31 -> conflict-free.
    unsigned int s = 0;
    #pragma unroll
    for (int i = 0; i < 32; i++) {
        int j = (t + i) & 31;
        s = __dp4a(sh32[t * 32 + j], 0x01010101u, s);
    }
    // store: [part][batch][bin=t]  (coalesced over t)
    g_part[(part * BATCH + batch) * BINS + t] = (float)s;
}

// ---------------------------------------------------------------------------
// Kernel 2: MLP, PARALLELIZED. 128 blocks (one per batch) x 128 threads (one
// per bin). R6's single-block version serialized 2048 dependent LDGs per
// thread on one SM (~196us!). Here: 16 independent coalesced loads/thread,
// 16 FMAs, then shfl+smem cross-bin reduction.
// ---------------------------------------------------------------------------
__global__ void __launch_bounds__(BINS) mlp_kernel(const float* __restrict__ W1,
                                                   const float* __restrict__ b1,
                                                   const float* __restrict__ W2,
                                                   const float* __restrict__ b2) {
    const int b = blockIdx.x;
    const int k = threadIdx.x;          // bin
    const int lane = k & 31;
    const int warp = k >> 5;

    // hist[b][k] = sum over parts (16 independent coalesced loads)
    float c = 0.0f;
    #pragma unroll
    for (int p = 0; p < HIST_BPB; p++)
        c += g_part[(p * BATCH + b) * BINS + k];

    // partial products for all 16 hidden units
    float hp[16];
    #pragma unroll
    for (int j = 0; j < 16; j++)
        hp[j] = c * W1[k * 16 + j];

    // warp-level sum over k within each warp (butterfly)
    #pragma unroll
    for (int j = 0; j < 16; j++) {
        #pragma unroll
        for (int off = 16; off >= 1; off >>= 1)
            hp[j] += __shfl_xor_sync(0xFFFFFFFFu, hp[j], off);
    }

    __shared__ float sh_h[4][16];
    if (lane == 0) {
        #pragma unroll
        for (int j = 0; j < 16; j++)
            sh_h[warp][j] = hp[j];
    }
    __syncthreads();

    if (k < 32) {
        float v = 0.0f;
        if (k < 16) {
            float h = sh_h[0][k] + sh_h[1][k] + sh_h[2][k] + sh_h[3][k] + b1[k];
            v = fmaxf(h, 0.0f) * W2[k];
        }
        // sum lanes 0..15 (lanes 16..31 hold 0; xor offsets <16 stay in-group)
        #pragma unroll
        for (int off = 8; off >= 1; off >>= 1)
            v += __shfl_xor_sync(0xFFFFFFFFu, v, off);
        if (k == 0)
            g_w[b] = v + b2[0];
    }
}

// ---------------------------------------------------------------------------
// Kernel 3: out = x * w[batch]. float4 vectorized; 65536 float4 per batch so
// batch = vec_idx >> 16 (warp-uniform).
// ---------------------------------------------------------------------------
__global__ void __launch_bounds__(256) scale_kernel(const float* __restrict__ x,
                                                    float* __restrict__ out) {
    size_t vi = (size_t)blockIdx.x * blockDim.x + threadIdx.x;
    float w = g_w[vi >> 16];
    float4 v = reinterpret_cast<const float4*>(x)[vi];
    v.x *= w; v.y *= w; v.z *= w; v.w *= w;
    reinterpret_cast<float4*>(out)[vi] = v;
}

// ---------------------------------------------------------------------------
// Launch
// ---------------------------------------------------------------------------
extern "C" void kernel_launch(void* const* d_in, const int* in_sizes, int n_in,
                              void* d_out, int out_size) {
    const float* x  = (const float*)d_in[0];
    const float* W1 = (const float*)d_in[1];
    const float* b1 = (const float*)d_in[2];
    const float* W2 = (const float*)d_in[3];
    const float* b2 = (const float*)d_in[4];
    float* out = (float*)d_out;

    hist_kernel<<<BATCH * HIST_BPB, HIST_THREADS>>>(x);
    mlp_kernel<<<BATCH, BINS>>>(W1, b1, W2, b2);
    scale_kernel<<<(TOTAL / 4) / 256, 256>>>(x, out);
}

// round 9
// speedup vs baseline: 3.7268x; 1.0911x over previous
#include <cuda_runtime.h>
#include <cuda_bf16.h>

// Problem constants
#define BATCH 128
#define BINS 128
#define HW 262144               // 512*512 elements per batch (C=1)
#define TOTAL (BATCH * HW)      // 33554432
#define HIST_BPB 16             // histogram blocks per batch
#define HIST_THREADS 256
#define CHUNK (HW / HIST_BPB)   // 16384 elements per hist block

// Scratch (device globals: no allocations allowed)
// Layout: g_part[part][batch][bin] -> hist epilogue store coalesced over bin,
// MLP per-bin loads coalesced over bin (thread = bin).
__device__ float g_part[HIST_BPB * BATCH * BINS];
__device__ float g_w[BATCH];

// ---------------------------------------------------------------------------
// Kernel 1: per-batch histogram.
// 256 threads/block, per-thread private UINT8 counters, 32 KB smem ->
// 7 blocks/SM = 1792 threads/SM (vs 1664 in R7) and the per-thread serial
// RMW chain halves (64 elements/thread). Conflict-free layout:
//   counter(bin, t) at byte  bin*256 + (t&31)*4 + ((t>>5)&3) + (t>>7)*128
// -> word index = bin*64 + (t&31) + (t>>7)*32, bank = t&31: distinct per
//    lane within every warp, independent of bin. Warps 0-3 share words with
//    each other only byte-wise (different bytes), same for warps 4-7.
// 64 elements/thread -> uint8 cannot overflow.
// ---------------------------------------------------------------------------
__global__ void __launch_bounds__(HIST_THREADS) hist_kernel(const float* __restrict__ x) {
    __shared__ unsigned char sh[BINS * 256];             // 32 KB
    unsigned int* sh32 = reinterpret_cast<unsigned int*>(sh);

    const int t = threadIdx.x;

    // zero: 8192 words / 256 threads = 32 each, bank = t&31: conflict-free
    #pragma unroll
    for (int i = 0; i < 32; i++)
        sh32[i * 256 + t] = 0u;
    __syncthreads();

    const int batch = blockIdx.x >> 4;              // / HIST_BPB
    const int part  = blockIdx.x & (HIST_BPB - 1);
    const int lane_off = (t & 31) * 4 + ((t >> 5) & 3) + (t >> 7) * 128;

    const float4* xp = reinterpret_cast<const float4*>(x)
                     + (size_t)batch * (HW / 4) + (size_t)part * (CHUNK / 4);

    // CHUNK/4 = 4096 float4 per block, 256 threads -> 16 iterations
    #pragma unroll 8
    for (int i = t; i < CHUNK / 4; i += HIST_THREADS) {
        float4 v = xp[i];
        {
            float g = v.x * 128.0f;                  // exact (x * 2^7)
            int bin = min(__float2int_rd(g), BINS - 1);
            if (g >= 0.0f && g <= 128.0f) sh[bin * 256 + lane_off]++;
        }
        {
            float g = v.y * 128.0f;
            int bin = min(__float2int_rd(g), BINS - 1);
            if (g >= 0.0f && g <= 128.0f) sh[bin * 256 + lane_off]++;
        }
        {
            float g = v.z * 128.0f;
            int bin = min(__float2int_rd(g), BINS - 1);
            if (g >= 0.0f && g <= 128.0f) sh[bin * 256 + lane_off]++;
        }
        {
            float g = v.w * 128.0f;
            int bin = min(__float2int_rd(g), BINS - 1);
            if (g >= 0.0f && g <= 128.0f) sh[bin * 256 + lane_off]++;
        }
    }
    __syncthreads();

    // Reduce: thread t (t<128) sums bin t's 256 counters = 64 words x 4 bytes
    // (dp4a). Rotated read j=(t+i)&63 -> bank (t+i)&31: distinct per lane.
    if (t < BINS) {
        unsigned int s = 0;
        #pragma unroll
        for (int i = 0; i < 64; i++) {
            int j = (t + i) & 63;
            s = __dp4a(sh32[t * 64 + j], 0x01010101u, s);
        }
        // store: [part][batch][bin=t]  (coalesced over t)
        g_part[(part * BATCH + batch) * BINS + t] = (float)s;
    }
}

// ---------------------------------------------------------------------------
// Kernel 2: MLP. 128 blocks (one per batch) x 128 threads (one per bin).
// 16 independent coalesced loads/thread, 16 FMAs, shfl+smem reduction.
// ---------------------------------------------------------------------------
__global__ void __launch_bounds__(BINS) mlp_kernel(const float* __restrict__ W1,
                                                   const float* __restrict__ b1,
                                                   const float* __restrict__ W2,
                                                   const float* __restrict__ b2) {
    const int b = blockIdx.x;
    const int k = threadIdx.x;          // bin
    const int lane = k & 31;
    const int warp = k >> 5;

    // hist[b][k] = sum over parts (16 independent coalesced loads)
    float c = 0.0f;
    #pragma unroll
    for (int p = 0; p < HIST_BPB; p++)
        c += g_part[(p * BATCH + b) * BINS + k];

    // partial products for all 16 hidden units
    float hp[16];
    #pragma unroll
    for (int j = 0; j < 16; j++)
        hp[j] = c * W1[k * 16 + j];

    // warp-level sum over k within each warp (butterfly)
    #pragma unroll
    for (int j = 0; j < 16; j++) {
        #pragma unroll
        for (int off = 16; off >= 1; off >>= 1)
            hp[j] += __shfl_xor_sync(0xFFFFFFFFu, hp[j], off);
    }

    __shared__ float sh_h[4][16];
    if (lane == 0) {
        #pragma unroll
        for (int j = 0; j < 16; j++)
            sh_h[warp][j] = hp[j];
    }
    __syncthreads();

    if (k < 32) {
        float v = 0.0f;
        if (k < 16) {
            float h = sh_h[0][k] + sh_h[1][k] + sh_h[2][k] + sh_h[3][k] + b1[k];
            v = fmaxf(h, 0.0f) * W2[k];
        }
        #pragma unroll
        for (int off = 8; off >= 1; off >>= 1)
            v += __shfl_xor_sync(0xFFFFFFFFu, v, off);
        if (k == 0)
            g_w[b] = v + b2[0];
    }
}

// ---------------------------------------------------------------------------
// Kernel 3: out = x * w[batch].
// REVERSED block->chunk mapping: hist just streamed x through L2 (126 MB), so
// the TAIL of x is resident; first-scheduled blocks read it hot. Streaming
// stores (__stcs) keep the out write stream from evicting x's L2 lines.
// ---------------------------------------------------------------------------
__global__ void __launch_bounds__(256) scale_kernel(const float* __restrict__ x,
                                                    float* __restrict__ out) {
    size_t vi = (size_t)(gridDim.x - 1 - blockIdx.x) * blockDim.x + threadIdx.x;
    float w = g_w[vi >> 16];
    float4 v = reinterpret_cast<const float4*>(x)[vi];
    v.x *= w; v.y *= w; v.z *= w; v.w *= w;
    __stcs(reinterpret_cast<float4*>(out) + vi, v);
}

// ---------------------------------------------------------------------------
// Launch
// ---------------------------------------------------------------------------
extern "C" void kernel_launch(void* const* d_in, const int* in_sizes, int n_in,
                              void* d_out, int out_size) {
    const float* x  = (const float*)d_in[0];
    const float* W1 = (const float*)d_in[1];
    const float* b1 = (const float*)d_in[2];
    const float* W2 = (const float*)d_in[3];
    const float* b2 = (const float*)d_in[4];
    float* out = (float*)d_out;

    hist_kernel<<<BATCH * HIST_BPB, HIST_THREADS>>>(x);
    mlp_kernel<<<BATCH, BINS>>>(W1, b1, W2, b2);
    scale_kernel<<<(TOTAL / 4) / 256, 256>>>(x, out);
}

// round 13
// speedup vs baseline: 3.7451x; 1.0049x over previous
#include <cuda_runtime.h>
#include <cuda_bf16.h>

// Problem constants
#define BATCH 128
#define BINS 128
#define HW 262144               // 512*512 elements per batch (C=1)
#define TOTAL (BATCH * HW)      // 33554432
#define HIST_BPB 16             // histogram blocks per batch
#define HIST_THREADS 256
#define CHUNK (HW / HIST_BPB)   // 16384 elements per hist block

// Scratch (device globals: no allocations allowed)
__device__ float g_part[HIST_BPB * BATCH * BINS];   // [part][batch][bin]
__device__ float g_w[BATCH];

// 32-byte (8-float) global load with L2 evict_last policy. sm_103a ptxas
// only allows .L2::evict_last on .v8.b32 / .v4.b64 loads.
struct F8 { float f[8]; };
static __device__ __forceinline__ F8 ldg32_evict_last(const void* p) {
    unsigned long long a, b, c, d;
    asm volatile("ld.global.L2::evict_last.v4.b64 {%0,%1,%2,%3}, [%4];"
                 : "=l"(a), "=l"(b), "=l"(c), "=l"(d)
                 : "l"(p));
    F8 r;
    r.f[0] = __uint_as_float((unsigned)(a));       r.f[1] = __uint_as_float((unsigned)(a >> 32));
    r.f[2] = __uint_as_float((unsigned)(b));       r.f[3] = __uint_as_float((unsigned)(b >> 32));
    r.f[4] = __uint_as_float((unsigned)(c));       r.f[5] = __uint_as_float((unsigned)(c >> 32));
    r.f[6] = __uint_as_float((unsigned)(d));       r.f[7] = __uint_as_float((unsigned)(d >> 32));
    return r;
}

// ---------------------------------------------------------------------------
// Kernel 1: per-batch histogram (R8 structure: 30.4us, occ 64%).
// 256 threads/block, per-thread private UINT8 counters, 32 KB smem.
// Conflict-free: counter(bin,t) at byte bin*256 + (t&31)*4 + ((t>>5)&3)
//   + (t>>7)*128  -> bank = t&31, independent of bin.
// 64 elements/thread -> uint8 cannot overflow.
// x loaded via 32B evict_last loads so x stays resident in L2 for the scale
// pass (x=134MB vs L2=126MB).
// ---------------------------------------------------------------------------
__global__ void __launch_bounds__(HIST_THREADS) hist_kernel(const float* __restrict__ x) {
    __shared__ unsigned char sh[BINS * 256];             // 32 KB
    unsigned int* sh32 = reinterpret_cast<unsigned int*>(sh);

    const int t = threadIdx.x;

    // zero: 8192 words / 256 threads = 32 each, bank = t&31: conflict-free
    #pragma unroll
    for (int i = 0; i < 32; i++)
        sh32[i * 256 + t] = 0u;
    __syncthreads();

    const int batch = blockIdx.x >> 4;              // / HIST_BPB
    const int part  = blockIdx.x & (HIST_BPB - 1);
    const int lane_off = (t & 31) * 4 + ((t >> 5) & 3) + (t >> 7) * 128;

    const char* xp = reinterpret_cast<const char*>(x)
                   + ((size_t)batch * HW + (size_t)part * CHUNK) * 4;

    // CHUNK/8 = 2048 8-float groups per block, 256 threads -> 8 iterations
    #pragma unroll 8
    for (int i = t; i < CHUNK / 8; i += HIST_THREADS) {
        F8 v = ldg32_evict_last(xp + (size_t)i * 32);
        #pragma unroll
        for (int e = 0; e < 8; e++) {
            float g = v.f[e] * 128.0f;               // exact (x * 2^7)
            int bin = min(__float2int_rd(g), BINS - 1);
            if (g >= 0.0f && g <= 128.0f) sh[bin * 256 + lane_off]++;
        }
    }
    __syncthreads();

    // Reduce: thread t (t<128) sums bin t's 256 counters = 64 words x 4 bytes
    // (dp4a). Rotated read j=(t+i)&63 -> bank (t+i)&31: distinct per lane.
    if (t < BINS) {
        unsigned int s = 0;
        #pragma unroll
        for (int i = 0; i < 64; i++) {
            int j = (t + i) & 63;
            s = __dp4a(sh32[t * 64 + j], 0x01010101u, s);
        }
        g_part[(part * BATCH + batch) * BINS + t] = (float)s;
    }
}

// ---------------------------------------------------------------------------
// Kernel 2: MLP. 128 blocks (one per batch) x 128 threads (one per bin).
// ---------------------------------------------------------------------------
__global__ void __launch_bounds__(BINS) mlp_kernel(const float* __restrict__ W1,
                                                   const float* __restrict__ b1,
                                                   const float* __restrict__ W2,
                                                   const float* __restrict__ b2) {
    const int b = blockIdx.x;
    const int k = threadIdx.x;          // bin
    const int lane = k & 31;
    const int warp = k >> 5;

    float c = 0.0f;
    #pragma unroll
    for (int p = 0; p < HIST_BPB; p++)
        c += g_part[(p * BATCH + b) * BINS + k];

    float hp[16];
    #pragma unroll
    for (int j = 0; j < 16; j++)
        hp[j] = c * W1[k * 16 + j];

    #pragma unroll
    for (int j = 0; j < 16; j++) {
        #pragma unroll
        for (int off = 16; off >= 1; off >>= 1)
            hp[j] += __shfl_xor_sync(0xFFFFFFFFu, hp[j], off);
    }

    __shared__ float sh_h[4][16];
    if (lane == 0) {
        #pragma unroll
        for (int j = 0; j < 16; j++)
            sh_h[warp][j] = hp[j];
    }
    __syncthreads();

    if (k < 32) {
        float v = 0.0f;
        if (k < 16) {
            float h = sh_h[0][k] + sh_h[1][k] + sh_h[2][k] + sh_h[3][k] + b1[k];
            v = fmaxf(h, 0.0f) * W2[k];
        }
        #pragma unroll
        for (int off = 8; off >= 1; off >>= 1)
            v += __shfl_xor_sync(0xFFFFFFFFu, v, off);
        if (k == 0)
            g_w[b] = v + b2[0];
    }
}

// ---------------------------------------------------------------------------
// Kernel 3: out = x * w[batch].
// x read via __ldcs (evict-first: line is dead after this read, and must not
// displace evict_last x lines not yet read). out written via __stcs
// (evict-first: the write stream cannot push x out of L2).
// Reversed block order: tail of x is the most recently hist-touched.
// ---------------------------------------------------------------------------
__global__ void __launch_bounds__(256) scale_kernel(const float* __restrict__ x,
                                                    float* __restrict__ out) {
    size_t vi = (size_t)(gridDim.x - 1 - blockIdx.x) * blockDim.x + threadIdx.x;
    float w = g_w[vi >> 16];
    float4 v = __ldcs(reinterpret_cast<const float4*>(x) + vi);
    v.x *= w; v.y *= w; v.z *= w; v.w *= w;
    __stcs(reinterpret_cast<float4*>(out) + vi, v);
}

// ---------------------------------------------------------------------------
// Launch
// ---------------------------------------------------------------------------
extern "C" void kernel_launch(void* const* d_in, const int* in_sizes, int n_in,
                              void* d_out, int out_size) {
    const float* x  = (const float*)d_in[0];
    const float* W1 = (const float*)d_in[1];
    const float* b1 = (const float*)d_in[2];
    const float* W2 = (const float*)d_in[3];
    const float* b2 = (const float*)d_in[4];
    float* out = (float*)d_out;

    hist_kernel<<<BATCH * HIST_BPB, HIST_THREADS>>>(x);
    mlp_kernel<<<BATCH, BINS>>>(W1, b1, W2, b2);
    scale_kernel<<<(TOTAL / 4) / 256, 256>>>(x, out);
}